// round 16
// baseline (speedup 1.0000x reference)
#include <cuda_runtime.h>

// PWLU channelwise activation, scalar bounds ±2.3, n_points=7 (n_regions=6).
// x: [B=64, C=256, H=56, W=56] fp32; points: [C,7]; left_diffs/right_diffs: [C].
// out = fp[c][r] + (xn - r) * df[c][r],  xn=(x-sim_left)/region_len, r=clip int.
//
// FINAL (R12 config, converged optimum at ~7.06 TB/s effective HBM = 88% of
// spec for this 1:1 read:write stream):
//  - one CTA per (b,c) slice (16384 x 256 threads, 32 regs -> full occupancy)
//  - all x LDG.128s front-batched BEFORE the smem table build + barrier
//    (barrier overlaps loads already in flight; no CTA-entry read bubble)
//  - 8-entry (false_point, diff) LUT in smem, one LDS.64 per element
//  - evict-first streaming stores (__stcs): write-once data, keeps L2
//    capacity for the write drain (+1% DRAM vs default stores)
// Tested and rejected: multi-slice CTAs, software pipelining, __ldcs loads,
// 256-bit LDG/STG, TMA bulk stores, bulk L2 prefetch — all neutral or worse;
// DRAM duty cycle is controller-bound, not SM-bound.

#define BOUND_F 2.3f
#define N_POINTS 7
#define N_REGIONS 6
#define C_DIM 256
#define HW 3136            // 56*56
#define HW4 784            // HW/4
#define THREADS 256

__global__ __launch_bounds__(THREADS)
void pwlu_kernel(const float* __restrict__ x,
                 const float* __restrict__ points,
                 const float* __restrict__ left_diffs,
                 const float* __restrict__ right_diffs,
                 float* __restrict__ out) {
    const int bc = blockIdx.x;          // b*C + c
    const int c  = bc & (C_DIM - 1);
    const int tid = threadIdx.x;

    const float4* __restrict__ xin = reinterpret_cast<const float4*>(x + (size_t)bc * HW);
    float4* __restrict__ o         = reinterpret_cast<float4*>(out + (size_t)bc * HW);

    // 1) Front-batch ALL x loads first — DRAM traffic in flight immediately.
    float4 v0 = xin[tid];
    float4 v1 = xin[tid + 256];
    float4 v2 = xin[tid + 512];
    float4 v3;
    const bool has3 = (tid < HW4 - 768);    // tid < 16
    if (has3) v3 = xin[tid + 768];

    // 2) Per-channel (false_point, diff) table + barrier, overlapped with
    //    the x loads already in flight.
    __shared__ float2 tab[8];           // tab[r] = {fp[r], df[r]}
    if (tid < 8) {
        const float* p = points + c * N_POINTS;
        float fp, df;
        if (tid == 0)            { df = left_diffs[c];  fp = p[0] - df; }
        else if (tid == N_POINTS){ df = right_diffs[c]; fp = p[N_POINTS - 1]; }
        else                     { df = p[tid] - p[tid - 1]; fp = p[tid - 1]; }
        tab[tid] = make_float2(fp, df);
    }
    __syncthreads();

    const float region_len = (2.0f * BOUND_F) / (float)N_REGIONS;
    const float inv_rl     = (float)N_REGIONS / (2.0f * BOUND_F);
    const float sim_left   = -BOUND_F - region_len;
    const float clip_hi    = (float)(N_REGIONS + 1) * 1.001f;   // 7.007

    auto pwlu1 = [&](float xv) -> float {
        float xn = (xv - sim_left) * inv_rl;
        float rf = fminf(fmaxf(xn, 0.0f), clip_hi);
        int   r  = __float2int_rz(rf);
        float d  = xn - (float)r;
        float2 t = tab[r];
        return fmaf(d, t.y, t.x);
    };
    auto pwlu4 = [&](float4 v) -> float4 {
        float4 r;
        r.x = pwlu1(v.x); r.y = pwlu1(v.y);
        r.z = pwlu1(v.z); r.w = pwlu1(v.w);
        return r;
    };

    // 3) Compute + evict-first streaming stores.
    __stcs(&o[tid],       pwlu4(v0));
    __stcs(&o[tid + 256], pwlu4(v1));
    __stcs(&o[tid + 512], pwlu4(v2));
    if (has3) __stcs(&o[tid + 768], pwlu4(v3));
}

extern "C" void kernel_launch(void* const* d_in, const int* in_sizes, int n_in,
                              void* d_out, int out_size) {
    const float* x  = (const float*)d_in[0];
    const float* p  = (const float*)d_in[1];
    const float* ld = (const float*)d_in[2];
    const float* rd = (const float*)d_in[3];
    float* out = (float*)d_out;

    const int B = 64;
    const int n_blocks = B * C_DIM;     // 16384
    pwlu_kernel<<<n_blocks, THREADS>>>(x, p, ld, rd, out);
}

// round 17
// speedup vs baseline: 1.0040x; 1.0040x over previous
#include <cuda_runtime.h>

// PWLU channelwise activation, scalar bounds ±2.3, n_points=7 (n_regions=6).
// x: [B=64, C=256, H=56, W=56] fp32; points: [C,7]; left_diffs/right_diffs: [C].
// out = fp[c][r] + (xn - r) * df[c][r],  xn=(x-sim_left)/region_len, r=clip int.
//
// R16: R12 minus the CTA-wide barrier. EVERY warp redundantly writes the
// same 8-entry (fp, df) table to smem (identical values -> benign race),
// ordered write->read per-warp with __syncwarp() only. Warps are now fully
// independent: no warp's stores wait on another warp's slow load return,
// removing the slowest-warp coupling the __syncthreads imposed.
// Everything else identical to the converged optimum (one CTA per slice,
// front-batched LDG.128, smem LUT gather, evict-first __stcs stores).

#define BOUND_F 2.3f
#define N_POINTS 7
#define N_REGIONS 6
#define C_DIM 256
#define HW 3136            // 56*56
#define HW4 784            // HW/4
#define THREADS 256

__global__ __launch_bounds__(THREADS)
void pwlu_kernel(const float* __restrict__ x,
                 const float* __restrict__ points,
                 const float* __restrict__ left_diffs,
                 const float* __restrict__ right_diffs,
                 float* __restrict__ out) {
    const int bc  = blockIdx.x;         // b*C + c
    const int c   = bc & (C_DIM - 1);
    const int tid = threadIdx.x;
    const int lid = tid & 31;

    const float4* __restrict__ xin = reinterpret_cast<const float4*>(x + (size_t)bc * HW);
    float4* __restrict__ o         = reinterpret_cast<float4*>(out + (size_t)bc * HW);

    // 1) Front-batch ALL x loads first — DRAM traffic in flight immediately.
    float4 v0 = xin[tid];
    float4 v1 = xin[tid + 256];
    float4 v2 = xin[tid + 512];
    float4 v3;
    const bool has3 = (tid < HW4 - 768);    // tid < 16
    if (has3) v3 = xin[tid + 768];

    // 2) Table build: every warp writes the same values (benign race).
    //    Only per-warp ordering needed -> __syncwarp, no __syncthreads.
    __shared__ float2 tab[8];           // tab[r] = {fp[r], df[r]}
    if (lid < 8) {
        const float* p = points + c * N_POINTS;
        float fp, df;
        if (lid == 0)            { df = left_diffs[c];  fp = p[0] - df; }
        else if (lid == N_POINTS){ df = right_diffs[c]; fp = p[N_POINTS - 1]; }
        else                     { df = p[lid] - p[lid - 1]; fp = p[lid - 1]; }
        tab[lid] = make_float2(fp, df);
    }
    __syncwarp();

    const float region_len = (2.0f * BOUND_F) / (float)N_REGIONS;
    const float inv_rl     = (float)N_REGIONS / (2.0f * BOUND_F);
    const float sim_left   = -BOUND_F - region_len;
    const float clip_hi    = (float)(N_REGIONS + 1) * 1.001f;   // 7.007

    auto pwlu1 = [&](float xv) -> float {
        float xn = (xv - sim_left) * inv_rl;
        float rf = fminf(fmaxf(xn, 0.0f), clip_hi);
        int   r  = __float2int_rz(rf);
        float d  = xn - (float)r;
        float2 t = tab[r];
        return fmaf(d, t.y, t.x);
    };
    auto pwlu4 = [&](float4 v) -> float4 {
        float4 r;
        r.x = pwlu1(v.x); r.y = pwlu1(v.y);
        r.z = pwlu1(v.z); r.w = pwlu1(v.w);
        return r;
    };

    // 3) Compute + evict-first streaming stores (warp-independent drain).
    __stcs(&o[tid],       pwlu4(v0));
    __stcs(&o[tid + 256], pwlu4(v1));
    __stcs(&o[tid + 512], pwlu4(v2));
    if (has3) __stcs(&o[tid + 768], pwlu4(v3));
}

extern "C" void kernel_launch(void* const* d_in, const int* in_sizes, int n_in,
                              void* d_out, int out_size) {
    const float* x  = (const float*)d_in[0];
    const float* p  = (const float*)d_in[1];
    const float* ld = (const float*)d_in[2];
    const float* rd = (const float*)d_in[3];
    float* out = (float*)d_out;

    const int B = 64;
    const int n_blocks = B * C_DIM;     // 16384
    pwlu_kernel<<<n_blocks, THREADS>>>(x, p, ld, rd, out);
}